// round 6
// baseline (speedup 1.0000x reference)
#include <cuda_runtime.h>
#include <cuda_bf16.h>
#include <cstdint>

// LJ constants (match reference); sigma=1, cutoff=5
#define EPSILON 1.0f
#define SHIFT_F (4.0f * (1.0f/244140625.0f - 1.0f/15625.0f))

// Replicated accumulation scratch, L2-resident (12.8 MB static).
#define NREP 32
#define MAX_ATOMS 100000
#define REP_STRIDE (MAX_ATOMS + 128)   // divisible by 4
__device__ __align__(16) float g_scratch[NREP * REP_STRIDE];

// Exact-size zero: one float4 per thread, no loop.
__global__ void __launch_bounds__(256)
lj_zero_scratch_v4(int n_vec4) {
    int i = blockIdx.x * blockDim.x + threadIdx.x;
    if (i < n_vec4)
        reinterpret_cast<float4*>(g_scratch)[i] = make_float4(0.f, 0.f, 0.f, 0.f);
}

__device__ __forceinline__ float lj_half_e(float x, float y, float z) {
    float r2   = fmaf(x, x, fmaf(y, y, z * z));
    float inv2 = 1.0f / r2;
    float sr6  = inv2 * inv2 * inv2;
    float e    = 4.0f * EPSILON * fmaf(sr6, sr6, -sr6) - SHIFT_F;
    return 0.5f * e;
}

// 4 edges/thread: 3x LDG.128 dist + 2x LDG.128 idx + 8 REDG.
// Load-instruction overhead over the REDG lane floor drops to ~6%.
__global__ void __launch_bounds__(256)
lj_edge_kernel_rep4(const float4* __restrict__ dist4,
                    const int4*   __restrict__ atom_a4,
                    const int4*   __restrict__ atom_b4,
                    int n_quads) {
    int t = blockIdx.x * blockDim.x + threadIdx.x;
    if (t >= n_quads) return;

    int4 ia = atom_a4[t];
    int4 ib = atom_b4[t];

    float4 d0 = dist4[3 * t + 0];   // e0.xyz, e1.x
    float4 d1 = dist4[3 * t + 1];   // e1.yz,  e2.xy
    float4 d2 = dist4[3 * t + 2];   // e2.z,   e3.xyz

    float h0 = lj_half_e(d0.x, d0.y, d0.z);
    float h1 = lj_half_e(d0.w, d1.x, d1.y);
    float h2 = lj_half_e(d1.z, d1.w, d2.x);
    float h3 = lj_half_e(d2.y, d2.z, d2.w);

    // Per-thread replica (contention already fully relieved at NREP=32).
    float* rep = g_scratch + (t & (NREP - 1)) * REP_STRIDE;
    atomicAdd(rep + ia.x, h0);
    atomicAdd(rep + ib.x, h0);
    atomicAdd(rep + ia.y, h1);
    atomicAdd(rep + ib.y, h1);
    atomicAdd(rep + ia.z, h2);
    atomicAdd(rep + ib.z, h2);
    atomicAdd(rep + ia.w, h3);
    atomicAdd(rep + ib.w, h3);
}

// Scalar tail (defensive; E % 4 == 0 here).
__global__ void lj_edge_tail_rep(const float* __restrict__ dist,
                                 const int* __restrict__ atom_a,
                                 const int* __restrict__ atom_b,
                                 int start, int n_edges) {
    int i = start + blockIdx.x * blockDim.x + threadIdx.x;
    if (i >= n_edges) return;
    float h = lj_half_e(dist[3*i], dist[3*i+1], dist[3*i+2]);
    float* rep = g_scratch + (i & (NREP - 1)) * REP_STRIDE;
    atomicAdd(rep + atom_a[i], h);
    atomicAdd(rep + atom_b[i], h);
}

// Reduce NREP replicas -> out, 4 atoms/thread via float4.
__global__ void __launch_bounds__(256)
lj_reduce_kernel_v4(float* __restrict__ out, int n_atoms) {
    int t = blockIdx.x * blockDim.x + threadIdx.x;
    int base = 4 * t;
    if (base >= n_atoms) return;

    float4 s = make_float4(0.f, 0.f, 0.f, 0.f);
    #pragma unroll
    for (int r = 0; r < NREP; r++) {
        const float4 v = *reinterpret_cast<const float4*>(
            g_scratch + r * REP_STRIDE + base);
        s.x += v.x; s.y += v.y; s.z += v.z; s.w += v.w;
    }
    if (base + 3 < n_atoms) {
        *reinterpret_cast<float4*>(out + base) = s;
    } else {
        float sv[4] = {s.x, s.y, s.z, s.w};
        for (int k = 0; k < 4 && base + k < n_atoms; k++) out[base + k] = sv[k];
    }
}

// Fallback (atom count exceeds static scratch): direct atomics.
__global__ void lj_zero_out(float* __restrict__ out, int n) {
    int i = blockIdx.x * blockDim.x + threadIdx.x;
    if (i < n) out[i] = 0.0f;
}
__global__ void lj_edge_kernel_direct(const float* __restrict__ dist,
                                      const int* __restrict__ atom_a,
                                      const int* __restrict__ atom_b,
                                      float* __restrict__ out,
                                      int n_edges) {
    int i = blockIdx.x * blockDim.x + threadIdx.x;
    if (i >= n_edges) return;
    float h = lj_half_e(dist[3*i], dist[3*i+1], dist[3*i+2]);
    atomicAdd(out + atom_a[i], h);
    atomicAdd(out + atom_b[i], h);
}

extern "C" void kernel_launch(void* const* d_in, const int* in_sizes, int n_in,
                              void* d_out, int out_size) {
    const float* dist   = (const float*)d_in[0];
    const int*   atom_a = (const int*)d_in[1];   // JAX x64-disabled: int32
    const int*   atom_b = (const int*)d_in[2];
    float* out = (float*)d_out;

    int n_edges = in_sizes[1];
    int n_atoms = out_size;
    const int T = 256;

    if (n_atoms <= MAX_ATOMS) {
        int n_vec4 = (NREP * REP_STRIDE) / 4;
        lj_zero_scratch_v4<<<(n_vec4 + T - 1) / T, T>>>(n_vec4);

        int n_quads = n_edges / 4;
        if (n_quads > 0)
            lj_edge_kernel_rep4<<<(n_quads + T - 1) / T, T>>>(
                (const float4*)dist, (const int4*)atom_a, (const int4*)atom_b, n_quads);
        int done = n_quads * 4;
        if (done < n_edges) {
            int rem = n_edges - done;
            lj_edge_tail_rep<<<(rem + T - 1) / T, T>>>(dist, atom_a, atom_b, done, n_edges);
        }

        int n_aq = (n_atoms + 3) / 4;
        lj_reduce_kernel_v4<<<(n_aq + T - 1) / T, T>>>(out, n_atoms);
    } else {
        lj_zero_out<<<(n_atoms + T - 1) / T, T>>>(out, n_atoms);
        lj_edge_kernel_direct<<<(n_edges + T - 1) / T, T>>>(dist, atom_a, atom_b, out, n_edges);
    }
}

// round 7
// speedup vs baseline: 1.0539x; 1.0539x over previous
#include <cuda_runtime.h>
#include <cuda_bf16.h>
#include <cstdint>

// LJ constants (match reference); sigma=1, cutoff=5
#define EPSILON 1.0f
#define SHIFT_F (4.0f * (1.0f/244140625.0f - 1.0f/15625.0f))

// Replicated accumulation scratch, fully L2-resident (3.2 MB static).
// NREP=8: enough to kill per-address contention (ladder: NREP=1 edge≈85us,
// NREP>=16 edge≈70us identical), small enough that zero+reduce ≈ 3us total.
#define NREP 8
#define MAX_ATOMS 100000
#define REP_STRIDE (MAX_ATOMS + 128)   // divisible by 4
__device__ __align__(16) float g_scratch[NREP * REP_STRIDE];

// Exact-size zero: one float4 per thread.
__global__ void __launch_bounds__(256)
lj_zero_scratch_v4(int n_vec4) {
    int i = blockIdx.x * blockDim.x + threadIdx.x;
    if (i < n_vec4)
        reinterpret_cast<float4*>(g_scratch)[i] = make_float4(0.f, 0.f, 0.f, 0.f);
}

__device__ __forceinline__ float lj_half_e(float x, float y, float z) {
    float r2   = fmaf(x, x, fmaf(y, y, z * z));
    float inv2 = 1.0f / r2;
    float sr6  = inv2 * inv2 * inv2;
    float e    = 4.0f * EPSILON * fmaf(sr6, sr6, -sr6) - SHIFT_F;
    return 0.5f * e;
}

// Scalar 1-edge/thread (proven best form; kernel is REDG-lane-bound,
// vectorizing loads measured neutral twice).
__global__ void __launch_bounds__(256)
lj_edge_kernel_rep(const float* __restrict__ dist,
                   const int* __restrict__ atom_a,
                   const int* __restrict__ atom_b,
                   int n_edges) {
    int i = blockIdx.x * blockDim.x + threadIdx.x;
    if (i >= n_edges) return;

    float x = dist[3 * i + 0];
    float y = dist[3 * i + 1];
    float z = dist[3 * i + 2];
    float h = lj_half_e(x, y, z);

    int ia = atom_a[i];
    int ib = atom_b[i];

    float* rep = g_scratch + (i & (NREP - 1)) * REP_STRIDE;
    atomicAdd(rep + ia, h);   // RED.ADD, fire-and-forget
    atomicAdd(rep + ib, h);
}

// Reduce NREP replicas -> out, 4 atoms/thread via float4.
__global__ void __launch_bounds__(256)
lj_reduce_kernel_v4(float* __restrict__ out, int n_atoms) {
    int t = blockIdx.x * blockDim.x + threadIdx.x;
    int base = 4 * t;
    if (base >= n_atoms) return;

    float4 s = make_float4(0.f, 0.f, 0.f, 0.f);
    #pragma unroll
    for (int r = 0; r < NREP; r++) {
        const float4 v = *reinterpret_cast<const float4*>(
            g_scratch + r * REP_STRIDE + base);
        s.x += v.x; s.y += v.y; s.z += v.z; s.w += v.w;
    }
    if (base + 3 < n_atoms) {
        *reinterpret_cast<float4*>(out + base) = s;
    } else {
        float sv[4] = {s.x, s.y, s.z, s.w};
        for (int k = 0; k < 4 && base + k < n_atoms; k++) out[base + k] = sv[k];
    }
}

// Fallback (atom count exceeds static scratch): direct atomics.
__global__ void lj_zero_out(float* __restrict__ out, int n) {
    int i = blockIdx.x * blockDim.x + threadIdx.x;
    if (i < n) out[i] = 0.0f;
}
__global__ void lj_edge_kernel_direct(const float* __restrict__ dist,
                                      const int* __restrict__ atom_a,
                                      const int* __restrict__ atom_b,
                                      float* __restrict__ out,
                                      int n_edges) {
    int i = blockIdx.x * blockDim.x + threadIdx.x;
    if (i >= n_edges) return;
    float h = lj_half_e(dist[3*i], dist[3*i+1], dist[3*i+2]);
    atomicAdd(out + atom_a[i], h);
    atomicAdd(out + atom_b[i], h);
}

extern "C" void kernel_launch(void* const* d_in, const int* in_sizes, int n_in,
                              void* d_out, int out_size) {
    const float* dist   = (const float*)d_in[0];
    const int*   atom_a = (const int*)d_in[1];   // JAX x64-disabled: int32
    const int*   atom_b = (const int*)d_in[2];
    float* out = (float*)d_out;

    int n_edges = in_sizes[1];
    int n_atoms = out_size;
    const int T = 256;

    if (n_atoms <= MAX_ATOMS) {
        int n_vec4 = (NREP * REP_STRIDE) / 4;
        lj_zero_scratch_v4<<<(n_vec4 + T - 1) / T, T>>>(n_vec4);
        lj_edge_kernel_rep<<<(n_edges + T - 1) / T, T>>>(dist, atom_a, atom_b, n_edges);
        int n_aq = (n_atoms + 3) / 4;
        lj_reduce_kernel_v4<<<(n_aq + T - 1) / T, T>>>(out, n_atoms);
    } else {
        lj_zero_out<<<(n_atoms + T - 1) / T, T>>>(out, n_atoms);
        lj_edge_kernel_direct<<<(n_edges + T - 1) / T, T>>>(dist, atom_a, atom_b, out, n_edges);
    }
}